// round 1
// baseline (speedup 1.0000x reference)
#include <cuda_runtime.h>
#include <cuda_bf16.h>

#define kT 20000
#define kE 300
#define kS 400
#define kH 150
#define NSPANS (10 * kT - 45)

// Scratch (allocation-free rule: __device__ globals)
__device__ float g_Ha[kT * kH];
__device__ float g_Hb[kT * kH];
__device__ float g_attn[kT];
__device__ float g_A[kT * kH];
__device__ float g_B[kT * kH];
__device__ float g_E[kT * kH];

// ---------------------------------------------------------------------------
// Tiled SGEMM: C[M,N] = A[M,K] @ B[K,N] (+bias) (+relu), row-major everywhere
// ---------------------------------------------------------------------------
#define BM 64
#define BN 64
#define BK 16

__global__ __launch_bounds__(256) void sgemm_kernel(
    int M, int N, int K,
    const float* __restrict__ A, const float* __restrict__ B,
    const float* __restrict__ bias, int relu,
    float* __restrict__ C)
{
    __shared__ __align__(16) float As[BK][BM + 4];  // +4 pad: 68-stride keeps 16B align, kills STS conflicts
    __shared__ __align__(16) float Bs[BK][BN];

    int tid = threadIdx.x;
    int m0 = blockIdx.x * BM;
    int n0 = blockIdx.y * BN;
    int tx = tid & 15;        // micro col group
    int ty = tid >> 4;        // micro row group

    int a_k = tid & 15;           // k within tile for A loads
    int a_m = (tid >> 4) * 4;     // base m for A loads
    int b_n = tid & 63;           // n for B loads
    int b_k = (tid >> 6) * 4;     // base k for B loads

    float acc[4][4] = {};

    for (int k0 = 0; k0 < K; k0 += BK) {
        #pragma unroll
        for (int i = 0; i < 4; i++) {
            int m = a_m + i;
            float v = 0.f;
            if (m0 + m < M && k0 + a_k < K)
                v = A[(size_t)(m0 + m) * K + k0 + a_k];
            As[a_k][m] = v;
        }
        #pragma unroll
        for (int i = 0; i < 4; i++) {
            int k = b_k + i;
            float v = 0.f;
            if (k0 + k < K && n0 + b_n < N)
                v = B[(size_t)(k0 + k) * N + n0 + b_n];
            Bs[k][b_n] = v;
        }
        __syncthreads();

        #pragma unroll
        for (int k = 0; k < BK; k++) {
            float4 av = *(const float4*)&As[k][ty * 4];
            float4 bv = *(const float4*)&Bs[k][tx * 4];
            float a[4] = {av.x, av.y, av.z, av.w};
            float b[4] = {bv.x, bv.y, bv.z, bv.w};
            #pragma unroll
            for (int i = 0; i < 4; i++)
                #pragma unroll
                for (int j = 0; j < 4; j++)
                    acc[i][j] = fmaf(a[i], b[j], acc[i][j]);
        }
        __syncthreads();
    }

    #pragma unroll
    for (int i = 0; i < 4; i++) {
        int m = m0 + ty * 4 + i;
        if (m >= M) continue;
        #pragma unroll
        for (int j = 0; j < 4; j++) {
            int n = n0 + tx * 4 + j;
            if (n >= N) continue;
            float v = acc[i][j];
            if (bias) v += bias[n];
            if (relu) v = fmaxf(v, 0.f);
            C[(size_t)m * N + n] = v;
        }
    }
}

// ---------------------------------------------------------------------------
// Attention output layer: logit[t] = Hb[t,:] . W3 + b3  (warp per token)
// ---------------------------------------------------------------------------
__global__ void attn_out_kernel(const float* __restrict__ Hb,
                                const float* __restrict__ W3,
                                const float* __restrict__ b3,
                                float* __restrict__ out, int M)
{
    int gwarp = (blockIdx.x * blockDim.x + threadIdx.x) >> 5;
    int lane = threadIdx.x & 31;
    if (gwarp >= M) return;
    float acc = 0.f;
    #pragma unroll
    for (int k = lane; k < kH; k += 32)
        acc = fmaf(Hb[(size_t)gwarp * kH + k], W3[k], acc);
    #pragma unroll
    for (int o = 16; o > 0; o >>= 1)
        acc += __shfl_down_sync(0xffffffffu, acc, o);
    if (lane == 0) out[gwarp] = acc + b3[0];
}

// ---------------------------------------------------------------------------
// Fused span kernel: softmax pool + h1 assembly + 150x150 matvec + W3 dot.
// Thread h owns W2 column h in registers (150 regs).
// ---------------------------------------------------------------------------
__global__ __launch_bounds__(160, 2) void span_kernel(
    const float* __restrict__ attn, const float* __restrict__ Am,
    const float* __restrict__ Bm, const float* __restrict__ Em,
    const float* __restrict__ W2, const float* __restrict__ b2,
    const float* __restrict__ W3, const float* __restrict__ b3,
    float* __restrict__ out, int total, int spb)
{
    int h = threadIdx.x;
    bool act = (h < kH);
    int hc = act ? h : 0;

    float rW2[kH];
    #pragma unroll
    for (int k = 0; k < kH; k++) rW2[k] = W2[k * kH + hc];
    float rW3 = act ? W3[hc] : 0.f;
    float rb2 = b2[hc];
    float b3v = b3[0];

    __shared__ float sh[kH];
    __shared__ float part[5];

    int start = blockIdx.x * spb;
    int end = min(start + spb, total);

    for (int id = start; id < end; id++) {
        // decode span id -> (width n, start s); offsets off(n)=(n-1)(T+1)-(n-1)n/2
        int n = 1, off = 0;
        #pragma unroll
        for (int m = 1; m < 10; m++) {
            int nxt = m * (kT + 1) - (m * (m + 1)) / 2;
            if (id >= nxt) { n = m + 1; off = nxt; }
        }
        int s = id - off;
        int e = s + n - 1;

        // softmax over attention logits inside the window (computed by every thread)
        float w[10];
        float mx = -1e30f;
        #pragma unroll
        for (int j = 0; j < 10; j++) {
            int idx = s + j; if (idx > kT - 1) idx = kT - 1;
            float v = (j < n) ? __ldg(&attn[idx]) : -1e30f;
            w[j] = v;
            mx = fmaxf(mx, v);
        }
        float sum = 0.f;
        #pragma unroll
        for (int j = 0; j < 10; j++) {
            float t = (j < n) ? __expf(w[j] - mx) : 0.f;
            w[j] = t;
            sum += t;
        }
        float inv = 1.f / sum;

        // h1[h] = relu(A[s] + B[e] + sum_j w_j * E[s+j])   (sc_b1 folded into A)
        if (act) {
            float h1v = Am[(size_t)s * kH + h] + Bm[(size_t)e * kH + h];
            #pragma unroll
            for (int j = 0; j < 10; j++)
                if (j < n)
                    h1v = fmaf(w[j] * inv, Em[(size_t)(s + j) * kH + h], h1v);
            sh[h] = fmaxf(h1v, 0.f);
        }
        __syncthreads();

        // h2[h] = relu(h1 . W2[:,h] + b2[h]);  val = h2[h] * W3[h]
        float acc = rb2;
        #pragma unroll
        for (int k = 0; k < kH; k++)
            acc = fmaf(sh[k], rW2[k], acc);
        float val = act ? fmaxf(acc, 0.f) * rW3 : 0.f;

        #pragma unroll
        for (int o = 16; o > 0; o >>= 1)
            val += __shfl_down_sync(0xffffffffu, val, o);
        if ((h & 31) == 0) part[h >> 5] = val;
        __syncthreads();
        if (h == 0)
            out[id] = part[0] + part[1] + part[2] + part[3] + part[4] + b3v;
    }
}

// ---------------------------------------------------------------------------
extern "C" void kernel_launch(void* const* d_in, const int* in_sizes, int n_in,
                              void* d_out, int out_size)
{
    const float* embeds = (const float*)d_in[0];
    const float* states = (const float*)d_in[1];
    const float* aW1 = (const float*)d_in[2];
    const float* ab1 = (const float*)d_in[3];
    const float* aW2 = (const float*)d_in[4];
    const float* ab2 = (const float*)d_in[5];
    const float* aW3 = (const float*)d_in[6];
    const float* ab3 = (const float*)d_in[7];
    const float* sW1 = (const float*)d_in[8];
    const float* sb1 = (const float*)d_in[9];
    const float* sW2 = (const float*)d_in[10];
    const float* sb2 = (const float*)d_in[11];
    const float* sW3 = (const float*)d_in[12];
    const float* sb3 = (const float*)d_in[13];
    float* out = (float*)d_out;

    float *Ha, *Hb, *attn, *Am, *Bm, *Em;
    cudaGetSymbolAddress((void**)&Ha, g_Ha);
    cudaGetSymbolAddress((void**)&Hb, g_Hb);
    cudaGetSymbolAddress((void**)&attn, g_attn);
    cudaGetSymbolAddress((void**)&Am, g_A);
    cudaGetSymbolAddress((void**)&Bm, g_B);
    cudaGetSymbolAddress((void**)&Em, g_E);

    dim3 gtok((kT + BM - 1) / BM, (kH + BN - 1) / BN);

    // attention MLP over tokens
    sgemm_kernel<<<gtok, 256>>>(kT, kH, kS, states, aW1, ab1, 1, Ha);
    sgemm_kernel<<<gtok, 256>>>(kT, kH, kH, Ha, aW2, ab2, 1, Hb);
    attn_out_kernel<<<(kT + 7) / 8, 256>>>(Hb, aW3, ab3, attn, kT);

    // scorer layer-1 factorization: A (start-state, +b1), B (end-state), E (embeds)
    sgemm_kernel<<<gtok, 256>>>(kT, kH, kS, states, sW1, sb1, 0, Am);
    sgemm_kernel<<<gtok, 256>>>(kT, kH, kS, states, sW1 + (size_t)400 * kH, nullptr, 0, Bm);
    sgemm_kernel<<<gtok, 256>>>(kT, kH, kE, embeds, sW1 + (size_t)800 * kH, nullptr, 0, Em);

    // fused span scoring
    int grid = 1480;
    int spb = (NSPANS + grid - 1) / grid;
    span_kernel<<<grid, 160>>>(attn, Am, Bm, Em, sW2, sb2, sW3, sb3, out, NSPANS, spb);
}

// round 2
// speedup vs baseline: 1.2945x; 1.2945x over previous
#include <cuda_runtime.h>
#include <cuda_bf16.h>

#define kT 20000
#define kE 300
#define kS 400
#define kH 150
#define NSPANS (10 * kT - 45)
#define TOKW 450   // [Ha | A | B] per token

typedef unsigned long long ull;

// Scratch (allocation-free rule: __device__ globals)
__device__ float g_tok[(size_t)kT * TOKW];   // cols 0:150 Ha, 150:300 A(start,+b1), 300:450 B(end)
__device__ float g_Hb[(size_t)kT * kH];
__device__ float g_E[(size_t)kT * kH];
__device__ float g_attn[kT];

// ---------------------------------------------------------------------------
// SGEMM 128x128x8, 8x8 microtile, f32x2-packed FMA. Weights are [K x 150]
// row-major; up to 3 column segments of width 150 (B0|B1|B2) for fusion.
// ---------------------------------------------------------------------------
#define GBM 128
#define GBN 128
#define GBK 8

__global__ __launch_bounds__(256) void sgemm2(
    int M, int N, int K,
    const float* __restrict__ A, int lda,
    const float* __restrict__ B0, const float* __restrict__ B1,
    const float* __restrict__ B2,
    const float* __restrict__ bias0, const float* __restrict__ bias1,
    int relu_mask,
    float* __restrict__ C, int ldc)
{
    __shared__ __align__(16) float As[GBK][132];
    __shared__ __align__(16) float Bs[GBK][GBN];

    int tid = threadIdx.x;
    int m0 = blockIdx.x * GBM, n0 = blockIdx.y * GBN;
    int ty = tid >> 4, tx = tid & 15;     // 16x16 threads, 8x8 micro
    int ar = tid >> 1;                    // A load row (0..127)
    int ac = (tid & 1) * 4;               // A load col base
    int bk = tid >> 5;                    // B load k row (0..7)
    int bn = (tid & 31) * 4;              // B load col base

    ull acc[8][4] = {};

    for (int k0 = 0; k0 < K; k0 += GBK) {
        #pragma unroll
        for (int i = 0; i < 4; i++) {
            float v = 0.f;
            int kk = k0 + ac + i;
            if (m0 + ar < M && kk < K)
                v = A[(size_t)(m0 + ar) * lda + kk];
            As[ac + i][ar] = v;
        }
        {
            float4 bv = {0.f, 0.f, 0.f, 0.f};
            float* bvp = (float*)&bv;
            int kk = k0 + bk;
            #pragma unroll
            for (int i = 0; i < 4; i++) {
                int n = n0 + bn + i;
                if (n < N && kk < K) {
                    int seg = n / 150;
                    int nn = n - seg * 150;
                    const float* Bp = (seg == 0) ? B0 : ((seg == 1) ? B1 : B2);
                    bvp[i] = Bp[(size_t)kk * 150 + nn];
                }
            }
            *(float4*)&Bs[bk][bn] = bv;
        }
        __syncthreads();

        #pragma unroll
        for (int k = 0; k < GBK; k++) {
            float4 a0 = *(const float4*)&As[k][ty * 8];
            float4 a1 = *(const float4*)&As[k][ty * 8 + 4];
            ulonglong2 bb0 = *(const ulonglong2*)&Bs[k][tx * 8];
            ulonglong2 bb1 = *(const ulonglong2*)&Bs[k][tx * 8 + 4];
            ull bp[4] = {bb0.x, bb0.y, bb1.x, bb1.y};
            float av[8] = {a0.x, a0.y, a0.z, a0.w, a1.x, a1.y, a1.z, a1.w};
            #pragma unroll
            for (int i = 0; i < 8; i++) {
                ull ap;
                unsigned ai = __float_as_uint(av[i]);
                asm("mov.b64 %0, {%1, %1};" : "=l"(ap) : "r"(ai));
                #pragma unroll
                for (int j = 0; j < 4; j++)
                    asm("fma.rn.f32x2 %0, %1, %2, %0;"
                        : "+l"(acc[i][j]) : "l"(ap), "l"(bp[j]));
            }
        }
        __syncthreads();
    }

    #pragma unroll
    for (int i = 0; i < 8; i++) {
        int m = m0 + ty * 8 + i;
        if (m >= M) continue;
        #pragma unroll
        for (int j = 0; j < 4; j++) {
            unsigned lo, hi;
            asm("mov.b64 {%0, %1}, %2;" : "=r"(lo), "=r"(hi) : "l"(acc[i][j]));
            float vv[2] = {__uint_as_float(lo), __uint_as_float(hi)};
            #pragma unroll
            for (int q = 0; q < 2; q++) {
                int n = n0 + tx * 8 + 2 * j + q;
                if (n >= N) continue;
                float v = vv[q];
                int seg = n / 150;
                if (seg == 0 && bias0) v += bias0[n];
                if (seg == 1 && bias1) v += bias1[n - 150];
                if ((relu_mask >> seg) & 1) v = fmaxf(v, 0.f);
                C[(size_t)m * ldc + n] = v;
            }
        }
    }
}

// ---------------------------------------------------------------------------
// Attention output layer: logit[t] = Hb[t,:] . W3 + b3  (warp per token)
// ---------------------------------------------------------------------------
__global__ void attn_out_kernel(const float* __restrict__ Hb,
                                const float* __restrict__ W3,
                                const float* __restrict__ b3,
                                float* __restrict__ out, int M)
{
    int gwarp = (blockIdx.x * blockDim.x + threadIdx.x) >> 5;
    int lane = threadIdx.x & 31;
    if (gwarp >= M) return;
    float acc = 0.f;
    #pragma unroll
    for (int k = lane; k < kH; k += 32)
        acc = fmaf(Hb[(size_t)gwarp * kH + k], W3[k], acc);
    #pragma unroll
    for (int o = 16; o > 0; o >>= 1)
        acc += __shfl_down_sync(0xffffffffu, acc, o);
    if (lane == 0) out[gwarp] = acc + b3[0];
}

// ---------------------------------------------------------------------------
// Span kernel v2: width-specialized (blockIdx.y = n-1), 8 spans per batch.
// Thread h owns W2 column h in registers. f32x2 matvec, batched softmax,
// smem-staged E rows.
// ---------------------------------------------------------------------------
#define CH 8
#define SPT 160

__global__ __launch_bounds__(SPT, 2) void span_kernel(
    const float* __restrict__ attn,
    const float* __restrict__ tok,   // [kT][450]
    const float* __restrict__ Em,    // [kT][150]
    const float* __restrict__ W2, const float* __restrict__ b2,
    const float* __restrict__ W3, const float* __restrict__ b3,
    float* __restrict__ out)
{
    int n = blockIdx.y + 1;
    int S = kT - n + 1;
    int chunk = (S + gridDim.x - 1) / gridDim.x;
    int sa = blockIdx.x * chunk;
    int sb = min(sa + chunk, S);
    int off = (n - 1) * (kT + 1) - (n * (n - 1)) / 2;

    int h = threadIdx.x;
    bool act = h < kH;
    int hc = act ? h : 0;

    float rW2[kH];
    #pragma unroll
    for (int k = 0; k < kH; k++) rW2[k] = W2[k * kH + hc];
    float rW3 = act ? W3[hc] : 0.f;
    ull accInit;
    {
        unsigned b2u = __float_as_uint(b2[hc]);
        asm("mov.b64 %0, {%1, %1};" : "=l"(accInit) : "r"(b2u));
    }
    float b3v = b3[0];

    __shared__ float Esm[17][SPT];              // staged E rows
    __shared__ __align__(16) float sh1[kH][12]; // h1, [k][span], stride 12 (48B)
    __shared__ float sw[CH][12];                // normalized softmax weights
    __shared__ float red[5][CH];                // per-warp partials

    for (int s0 = sa; s0 < sb; s0 += CH) {
        int nsp = min(CH, sb - s0);
        int rows = n + nsp - 1;

        // stage E rows s0 .. s0+rows-1
        if (act)
            for (int r = 0; r < rows; r++)
                Esm[r][h] = Em[(size_t)(s0 + r) * kH + h];

        // softmax weights: one thread per span
        if (h < nsp) {
            int s = s0 + h;
            float w[10];
            float mx = -1e30f;
            for (int j = 0; j < n; j++) {
                float v = attn[s + j];
                w[j] = v;
                mx = fmaxf(mx, v);
            }
            float sum = 0.f;
            for (int j = 0; j < n; j++) {
                float e = __expf(w[j] - mx);
                w[j] = e;
                sum += e;
            }
            float inv = 1.f / sum;
            for (int j = 0; j < n; j++) sw[h][j] = w[j] * inv;
        }
        __syncthreads();

        // phase 1: h1[h][sp] = relu(A[s] + B[s+n-1] + sum_j w_j E[s+j])
        if (act) {
            for (int sp = 0; sp < nsp; sp++) {
                int s = s0 + sp;
                float v = tok[(size_t)s * TOKW + 150 + h]
                        + tok[(size_t)(s + n - 1) * TOKW + 300 + h];
                for (int j = 0; j < n; j++)
                    v = fmaf(sw[sp][j], Esm[sp + j][h], v);
                sh1[h][sp] = fmaxf(v, 0.f);
            }
            for (int sp = nsp; sp < CH; sp++) sh1[h][sp] = 0.f;
        }
        __syncthreads();

        // phase 2: h2[h][sp] = relu(h1[:, sp] . W2[:, h] + b2[h]); val = h2*W3[h]
        ull acc[4];
        #pragma unroll
        for (int j = 0; j < 4; j++) acc[j] = accInit;
        #pragma unroll
        for (int k = 0; k < kH; k++) {
            ulonglong2 u01 = *(const ulonglong2*)&sh1[k][0];
            ulonglong2 u23 = *(const ulonglong2*)&sh1[k][4];
            ull wp;
            unsigned wu = __float_as_uint(rW2[k]);
            asm("mov.b64 %0, {%1, %1};" : "=l"(wp) : "r"(wu));
            asm("fma.rn.f32x2 %0, %1, %2, %0;" : "+l"(acc[0]) : "l"(wp), "l"(u01.x));
            asm("fma.rn.f32x2 %0, %1, %2, %0;" : "+l"(acc[1]) : "l"(wp), "l"(u01.y));
            asm("fma.rn.f32x2 %0, %1, %2, %0;" : "+l"(acc[2]) : "l"(wp), "l"(u23.x));
            asm("fma.rn.f32x2 %0, %1, %2, %0;" : "+l"(acc[3]) : "l"(wp), "l"(u23.y));
        }
        float val[CH];
        #pragma unroll
        for (int j = 0; j < 4; j++) {
            unsigned lo, hi;
            asm("mov.b64 {%0, %1}, %2;" : "=r"(lo), "=r"(hi) : "l"(acc[j]));
            val[2 * j]     = act ? fmaxf(__uint_as_float(lo), 0.f) * rW3 : 0.f;
            val[2 * j + 1] = act ? fmaxf(__uint_as_float(hi), 0.f) * rW3 : 0.f;
        }
        #pragma unroll
        for (int sp = 0; sp < CH; sp++)
            #pragma unroll
            for (int o = 16; o > 0; o >>= 1)
                val[sp] += __shfl_down_sync(0xffffffffu, val[sp], o);
        if ((h & 31) == 0) {
            int w = h >> 5;
            #pragma unroll
            for (int sp = 0; sp < CH; sp++) red[w][sp] = val[sp];
        }
        __syncthreads();
        if (h < nsp)
            out[off + s0 + h] =
                red[0][h] + red[1][h] + red[2][h] + red[3][h] + red[4][h] + b3v;
        // next-iter smem writers (Esm/sw) are separated from the red[] read by
        // program order in h<8 threads and the phase-0 __syncthreads.
    }
}

// ---------------------------------------------------------------------------
extern "C" void kernel_launch(void* const* d_in, const int* in_sizes, int n_in,
                              void* d_out, int out_size)
{
    const float* embeds = (const float*)d_in[0];
    const float* states = (const float*)d_in[1];
    const float* aW1 = (const float*)d_in[2];
    const float* ab1 = (const float*)d_in[3];
    const float* aW2 = (const float*)d_in[4];
    const float* ab2 = (const float*)d_in[5];
    const float* aW3 = (const float*)d_in[6];
    const float* ab3 = (const float*)d_in[7];
    const float* sW1 = (const float*)d_in[8];
    const float* sb1 = (const float*)d_in[9];
    const float* sW2 = (const float*)d_in[10];
    const float* sb2 = (const float*)d_in[11];
    const float* sW3 = (const float*)d_in[12];
    const float* sb3 = (const float*)d_in[13];
    float* out = (float*)d_out;

    float *tok, *Hb, *E, *attn;
    cudaGetSymbolAddress((void**)&tok, g_tok);
    cudaGetSymbolAddress((void**)&Hb, g_Hb);
    cudaGetSymbolAddress((void**)&E, g_E);
    cudaGetSymbolAddress((void**)&attn, g_attn);

    // E = embeds @ sW1[800:1100]  (independent, launch first)
    {
        dim3 g((kT + GBM - 1) / GBM, (kH + GBN - 1) / GBN);
        sgemm2<<<g, 256>>>(kT, kH, kE, embeds, kE,
                           sW1 + (size_t)800 * kH, nullptr, nullptr,
                           nullptr, nullptr, 0, E, kH);
    }
    // fused token GEMM: [Ha | A | B] = states @ [aW1 | sW1[0:400] | sW1[400:800]]
    {
        dim3 g((kT + GBM - 1) / GBM, (TOKW + GBN - 1) / GBN);
        sgemm2<<<g, 256>>>(kT, TOKW, kS, states, kS,
                           aW1, sW1, sW1 + (size_t)400 * kH,
                           ab1, sb1, 1, tok, TOKW);
    }
    // Hb = relu(Ha @ aW2 + ab2)
    {
        dim3 g((kT + GBM - 1) / GBM, (kH + GBN - 1) / GBN);
        sgemm2<<<g, 256>>>(kT, kH, kH, tok, TOKW,
                           aW2, nullptr, nullptr,
                           ab2, nullptr, 1, Hb, kH);
    }
    attn_out_kernel<<<(kT + 7) / 8, 256>>>(Hb, aW3, ab3, attn, kT);

    // fused span scoring
    span_kernel<<<dim3(296, 10), SPT>>>(attn, tok, E, sW2, sb2, sW3, sb3, out);
}

// round 3
// speedup vs baseline: 1.8782x; 1.4509x over previous
#include <cuda_runtime.h>
#include <cuda_bf16.h>

#define kT 20000
#define kE 300
#define kS 400
#define kH 150
#define NSPANS (10 * kT - 45)
#define TOKW 450    // [Ha | A | B] per token
#define H1W 152     // padded h1 row (cols 150,151 = 0)

typedef unsigned long long ull;

// Scratch (allocation-free rule: __device__ globals)
__device__ float g_tok[(size_t)kT * TOKW];
__device__ float g_Hb[(size_t)kT * kH];
__device__ float g_E[(size_t)kT * kH];
__device__ float g_attn[kT];
__device__ float g_H1[(size_t)NSPANS * H1W];

// ---------------------------------------------------------------------------
// SGEMM 128x128x8, 8x8 microtile, f32x2 FMA. Weights [K x 150] row-major;
// up to 3 column segments of width 150 for fusion.
// ---------------------------------------------------------------------------
#define GBM 128
#define GBN 128
#define GBK 8

__global__ __launch_bounds__(256) void sgemm2(
    int M, int N, int K,
    const float* __restrict__ A, int lda,
    const float* __restrict__ B0, const float* __restrict__ B1,
    const float* __restrict__ B2,
    const float* __restrict__ bias0, const float* __restrict__ bias1,
    int relu_mask,
    float* __restrict__ C, int ldc)
{
    __shared__ __align__(16) float As[GBK][132];
    __shared__ __align__(16) float Bs[GBK][GBN];

    int tid = threadIdx.x;
    int m0 = blockIdx.x * GBM, n0 = blockIdx.y * GBN;
    int ty = tid >> 4, tx = tid & 15;
    int ar = tid >> 1;
    int ac = (tid & 1) * 4;
    int bk = tid >> 5;
    int bn = (tid & 31) * 4;

    ull acc[8][4] = {};

    for (int k0 = 0; k0 < K; k0 += GBK) {
        #pragma unroll
        for (int i = 0; i < 4; i++) {
            float v = 0.f;
            int kk = k0 + ac + i;
            if (m0 + ar < M && kk < K)
                v = A[(size_t)(m0 + ar) * lda + kk];
            As[ac + i][ar] = v;
        }
        {
            float4 bv = {0.f, 0.f, 0.f, 0.f};
            float* bvp = (float*)&bv;
            int kk = k0 + bk;
            #pragma unroll
            for (int i = 0; i < 4; i++) {
                int n = n0 + bn + i;
                if (n < N && kk < K) {
                    int seg = n / 150;
                    int nn = n - seg * 150;
                    const float* Bp = (seg == 0) ? B0 : ((seg == 1) ? B1 : B2);
                    bvp[i] = Bp[(size_t)kk * 150 + nn];
                }
            }
            *(float4*)&Bs[bk][bn] = bv;
        }
        __syncthreads();

        #pragma unroll
        for (int k = 0; k < GBK; k++) {
            float4 a0 = *(const float4*)&As[k][ty * 8];
            float4 a1 = *(const float4*)&As[k][ty * 8 + 4];
            ulonglong2 bb0 = *(const ulonglong2*)&Bs[k][tx * 8];
            ulonglong2 bb1 = *(const ulonglong2*)&Bs[k][tx * 8 + 4];
            ull bp[4] = {bb0.x, bb0.y, bb1.x, bb1.y};
            float av[8] = {a0.x, a0.y, a0.z, a0.w, a1.x, a1.y, a1.z, a1.w};
            #pragma unroll
            for (int i = 0; i < 8; i++) {
                ull ap;
                unsigned ai = __float_as_uint(av[i]);
                asm("mov.b64 %0, {%1, %1};" : "=l"(ap) : "r"(ai));
                #pragma unroll
                for (int j = 0; j < 4; j++)
                    asm("fma.rn.f32x2 %0, %1, %2, %0;"
                        : "+l"(acc[i][j]) : "l"(ap), "l"(bp[j]));
            }
        }
        __syncthreads();
    }

    #pragma unroll
    for (int i = 0; i < 8; i++) {
        int m = m0 + ty * 8 + i;
        if (m >= M) continue;
        #pragma unroll
        for (int j = 0; j < 4; j++) {
            unsigned lo, hi;
            asm("mov.b64 {%0, %1}, %2;" : "=r"(lo), "=r"(hi) : "l"(acc[i][j]));
            float vv[2] = {__uint_as_float(lo), __uint_as_float(hi)};
            #pragma unroll
            for (int q = 0; q < 2; q++) {
                int n = n0 + tx * 8 + 2 * j + q;
                if (n >= N) continue;
                float v = vv[q];
                int seg = n / 150;
                if (seg == 0 && bias0) v += bias0[n];
                if (seg == 1 && bias1) v += bias1[n - 150];
                if ((relu_mask >> seg) & 1) v = fmaxf(v, 0.f);
                C[(size_t)m * ldc + n] = v;
            }
        }
    }
}

// ---------------------------------------------------------------------------
// Attention output layer: logit[t] = Hb[t,:] . W3 + b3  (warp per token)
// ---------------------------------------------------------------------------
__global__ void attn_out_kernel(const float* __restrict__ Hb,
                                const float* __restrict__ W3,
                                const float* __restrict__ b3,
                                float* __restrict__ out, int M)
{
    int gwarp = (blockIdx.x * blockDim.x + threadIdx.x) >> 5;
    int lane = threadIdx.x & 31;
    if (gwarp >= M) return;
    float acc = 0.f;
    #pragma unroll
    for (int k = lane; k < kH; k += 32)
        acc = fmaf(Hb[(size_t)gwarp * kH + k], W3[k], acc);
    #pragma unroll
    for (int o = 16; o > 0; o >>= 1)
        acc += __shfl_down_sync(0xffffffffu, acc, o);
    if (lane == 0) out[gwarp] = acc + b3[0];
}

// ---------------------------------------------------------------------------
// h1 assembly: width-specialized blocks, 8 spans per batch. Writes padded
// H1 rows [NSPANS][152] to global (cols 150,151 = 0).
// ---------------------------------------------------------------------------
#define CH 8

__global__ __launch_bounds__(160) void h1_kernel(
    const float* __restrict__ attn,
    const float* __restrict__ tok,   // [kT][450]
    const float* __restrict__ Em,    // [kT][150]
    float* __restrict__ H1)
{
    int n = blockIdx.y + 1;
    int S = kT - n + 1;
    int chunk = (S + gridDim.x - 1) / gridDim.x;
    int sa = blockIdx.x * chunk;
    int sb = min(sa + chunk, S);
    int off = (n - 1) * (kT + 1) - (n * (n - 1)) / 2;

    int h = threadIdx.x;
    bool act = h < kH;

    __shared__ float Esm[17][160];
    __shared__ float sw[CH][10];

    for (int s0 = sa; s0 < sb; s0 += CH) {
        int nsp = min(CH, sb - s0);
        int rows = n + nsp - 1;

        if (act)
            for (int r = 0; r < rows; r++)
                Esm[r][h] = Em[(size_t)(s0 + r) * kH + h];

        if (h < nsp) {
            int s = s0 + h;
            float w[10];
            float mx = -1e30f;
            for (int j = 0; j < n; j++) {
                float v = attn[s + j];
                w[j] = v;
                mx = fmaxf(mx, v);
            }
            float sum = 0.f;
            for (int j = 0; j < n; j++) {
                float e = __expf(w[j] - mx);
                w[j] = e;
                sum += e;
            }
            float inv = 1.f / sum;
            for (int j = 0; j < n; j++) sw[h][j] = w[j] * inv;
        }
        __syncthreads();

        if (act) {
            for (int sp = 0; sp < nsp; sp++) {
                int s = s0 + sp;
                float v = tok[(size_t)s * TOKW + 150 + h]
                        + tok[(size_t)(s + n - 1) * TOKW + 300 + h];
                for (int j = 0; j < n; j++)
                    v = fmaf(sw[sp][j], Esm[sp + j][h], v);
                H1[(size_t)(off + s0 + sp) * H1W + h] = fmaxf(v, 0.f);
            }
        } else if (h < H1W) {  // pad cols 150,151
            for (int sp = 0; sp < nsp; sp++)
                H1[(size_t)(off + s0 + sp) * H1W + h] = 0.f;
        }
        __syncthreads();
    }
}

// ---------------------------------------------------------------------------
// Score GEMM: out[m] = sum_h relu( relu_h1row[m] . W2[:,h] + b2[h] ) * W3[h] + b3
// M x 150 (pad 160) x 152.  128x160 tile, 8x10 microtile, 256 threads.
// A staged duplicated ({v,v} pairs) so the broadcast operand packs via LDS.64.
// ---------------------------------------------------------------------------
#define SBM 128
#define SBK 8

__global__ __launch_bounds__(256, 2) void score_gemm(
    const float* __restrict__ H1,
    const float* __restrict__ W2, const float* __restrict__ b2,
    const float* __restrict__ W3, const float* __restrict__ b3,
    float* __restrict__ out, int M)
{
    __shared__ __align__(16) float As2[SBK][2 * SBM + 8];  // duplicated pairs
    __shared__ __align__(16) float Bs[SBK][160];
    __shared__ float red[SBM][17];

    int tid = threadIdx.x;
    int m0 = blockIdx.x * SBM;
    int ty = tid >> 4;            // 0..15, 8 rows each
    int tx = tid & 15;            // 0..15, 10 cols each
    int ar = tid >> 1;            // 0..127
    int ac = (tid & 1) * 4;       // 0 or 4
    int bk = tid >> 5;            // 0..7
    int bn = (tid & 31) * 5;      // 0..155

    ull acc[8][5] = {};

    for (int k0 = 0; k0 < H1W; k0 += SBK) {
        // stage A (duplicated): rows m0+ar, k = k0+ac..+3
        {
            float4 av = {0.f, 0.f, 0.f, 0.f};
            if (m0 + ar < M)
                av = *(const float4*)&H1[(size_t)(m0 + ar) * H1W + k0 + ac];
            float* avp = (float*)&av;
            #pragma unroll
            for (int i = 0; i < 4; i++) {
                float2 d = {avp[i], avp[i]};
                *(float2*)&As2[ac + i][2 * ar] = d;
            }
        }
        // stage B (W2 with zero pad): Bs[bk][bn..bn+4]
        {
            int kk = k0 + bk;
            #pragma unroll
            for (int i = 0; i < 5; i++) {
                int nn = bn + i;
                float v = 0.f;
                if (kk < kH && nn < kH)
                    v = W2[(size_t)kk * kH + nn];
                Bs[bk][nn] = v;
            }
        }
        __syncthreads();

        #pragma unroll
        for (int k = 0; k < SBK; k++) {
            ull bv[5];
            #pragma unroll
            for (int j = 0; j < 5; j++)
                bv[j] = *(const ull*)&Bs[k][tx * 10 + 2 * j];
            #pragma unroll
            for (int i = 0; i < 8; i++) {
                ull av = *(const ull*)&As2[k][2 * (ty * 8 + i)];
                #pragma unroll
                for (int j = 0; j < 5; j++)
                    asm("fma.rn.f32x2 %0, %1, %2, %0;"
                        : "+l"(acc[i][j]) : "l"(av), "l"(bv[j]));
            }
        }
        __syncthreads();
    }

    // epilogue: per-row partial of sum_h relu(acc + b2)*W3
    float rb2[10], rw3[10];
    #pragma unroll
    for (int j = 0; j < 10; j++) {
        int c = tx * 10 + j;
        rb2[j] = (c < kH) ? b2[c] : 0.f;
        rw3[j] = (c < kH) ? W3[c] : 0.f;
    }
    #pragma unroll
    for (int i = 0; i < 8; i++) {
        float val = 0.f;
        #pragma unroll
        for (int j = 0; j < 5; j++) {
            unsigned lo, hi;
            asm("mov.b64 {%0, %1}, %2;" : "=r"(lo), "=r"(hi) : "l"(acc[i][j]));
            val = fmaf(fmaxf(__uint_as_float(lo) + rb2[2 * j], 0.f), rw3[2 * j], val);
            val = fmaf(fmaxf(__uint_as_float(hi) + rb2[2 * j + 1], 0.f), rw3[2 * j + 1], val);
        }
        red[ty * 8 + i][tx] = val;
    }
    __syncthreads();

    if (tid < SBM) {
        int m = m0 + tid;
        if (m < M) {
            float s = b3[0];
            #pragma unroll
            for (int t = 0; t < 16; t++) s += red[tid][t];
            out[m] = s;
        }
    }
}

// ---------------------------------------------------------------------------
extern "C" void kernel_launch(void* const* d_in, const int* in_sizes, int n_in,
                              void* d_out, int out_size)
{
    const float* embeds = (const float*)d_in[0];
    const float* states = (const float*)d_in[1];
    const float* aW1 = (const float*)d_in[2];
    const float* ab1 = (const float*)d_in[3];
    const float* aW2 = (const float*)d_in[4];
    const float* ab2 = (const float*)d_in[5];
    const float* aW3 = (const float*)d_in[6];
    const float* ab3 = (const float*)d_in[7];
    const float* sW1 = (const float*)d_in[8];
    const float* sb1 = (const float*)d_in[9];
    const float* sW2 = (const float*)d_in[10];
    const float* sb2 = (const float*)d_in[11];
    const float* sW3 = (const float*)d_in[12];
    const float* sb3 = (const float*)d_in[13];
    float* out = (float*)d_out;

    float *tok, *Hb, *E, *attn, *H1;
    cudaGetSymbolAddress((void**)&tok, g_tok);
    cudaGetSymbolAddress((void**)&Hb, g_Hb);
    cudaGetSymbolAddress((void**)&E, g_E);
    cudaGetSymbolAddress((void**)&attn, g_attn);
    cudaGetSymbolAddress((void**)&H1, g_H1);

    // E = embeds @ sW1[800:1100]
    {
        dim3 g((kT + GBM - 1) / GBM, (kH + GBN - 1) / GBN);
        sgemm2<<<g, 256>>>(kT, kH, kE, embeds, kE,
                           sW1 + (size_t)800 * kH, nullptr, nullptr,
                           nullptr, nullptr, 0, E, kH);
    }
    // fused token GEMM: [Ha | A | B] = states @ [aW1 | sW1[0:400] | sW1[400:800]]
    {
        dim3 g((kT + GBM - 1) / GBM, (TOKW + GBN - 1) / GBN);
        sgemm2<<<g, 256>>>(kT, TOKW, kS, states, kS,
                           aW1, sW1, sW1 + (size_t)400 * kH,
                           ab1, sb1, 1, tok, TOKW);
    }
    // Hb = relu(Ha @ aW2 + ab2)
    {
        dim3 g((kT + GBM - 1) / GBM, (kH + GBN - 1) / GBN);
        sgemm2<<<g, 256>>>(kT, kH, kH, tok, TOKW,
                           aW2, nullptr, nullptr,
                           ab2, nullptr, 1, Hb, kH);
    }
    attn_out_kernel<<<(kT + 7) / 8, 256>>>(Hb, aW3, ab3, attn, kT);

    // h1 assembly -> big H1 matrix
    h1_kernel<<<dim3(592, 10), 160>>>(attn, tok, E, H1);

    // score GEMM with fused layer-3 epilogue
    score_gemm<<<(NSPANS + SBM - 1) / SBM, 256>>>(H1, sW2, sb2, sW3, sb3,
                                                  out, NSPANS);
}

// round 4
// speedup vs baseline: 2.0824x; 1.1087x over previous
#include <cuda_runtime.h>
#include <cuda_bf16.h>

#define kT 20000
#define kE 300
#define kS 400
#define kH 150
#define NSPANS (10 * kT - 45)
#define TOKW 450    // [Ha | A | B] per token
#define H1P 160     // padded h1 row (cols 150..159 = 0)

typedef unsigned long long ull;

// Scratch (allocation-free rule: __device__ globals)
__device__ float g_tok[(size_t)kT * TOKW];
__device__ float g_Hb[(size_t)kT * kH];
__device__ float g_E[(size_t)kT * kH];
__device__ float g_attn[kT];
__device__ __nv_bfloat16 g_H1h[(size_t)NSPANS * H1P];
__device__ __nv_bfloat16 g_H1l[(size_t)NSPANS * H1P];
__device__ __nv_bfloat16 g_W2s[2 * H1P * H1P];   // [split][k][n] padded
__device__ float g_b2p[H1P];
__device__ float g_w3p[H1P];

static __device__ __forceinline__ unsigned sm_u32(const void* p) {
    return (unsigned)__cvta_generic_to_shared(p);
}

// ---------------------------------------------------------------------------
// SGEMM 128x128x8, 8x8 microtile, f32x2 FMA (token-level GEMMs).
// ---------------------------------------------------------------------------
#define GBM 128
#define GBN 128
#define GBK 8

__global__ __launch_bounds__(256) void sgemm2(
    int M, int N, int K,
    const float* __restrict__ A, int lda,
    const float* __restrict__ B0, const float* __restrict__ B1,
    const float* __restrict__ B2,
    const float* __restrict__ bias0, const float* __restrict__ bias1,
    int relu_mask,
    float* __restrict__ C, int ldc)
{
    __shared__ __align__(16) float As[GBK][132];
    __shared__ __align__(16) float Bs[GBK][GBN];

    int tid = threadIdx.x;
    int m0 = blockIdx.x * GBM, n0 = blockIdx.y * GBN;
    int ty = tid >> 4, tx = tid & 15;
    int ar = tid >> 1;
    int ac = (tid & 1) * 4;
    int bk = tid >> 5;
    int bn = (tid & 31) * 4;

    ull acc[8][4] = {};

    for (int k0 = 0; k0 < K; k0 += GBK) {
        #pragma unroll
        for (int i = 0; i < 4; i++) {
            float v = 0.f;
            int kk = k0 + ac + i;
            if (m0 + ar < M && kk < K)
                v = A[(size_t)(m0 + ar) * lda + kk];
            As[ac + i][ar] = v;
        }
        {
            float4 bv = {0.f, 0.f, 0.f, 0.f};
            float* bvp = (float*)&bv;
            int kk = k0 + bk;
            #pragma unroll
            for (int i = 0; i < 4; i++) {
                int n = n0 + bn + i;
                if (n < N && kk < K) {
                    int seg = n / 150;
                    int nn = n - seg * 150;
                    const float* Bp = (seg == 0) ? B0 : ((seg == 1) ? B1 : B2);
                    bvp[i] = Bp[(size_t)kk * 150 + nn];
                }
            }
            *(float4*)&Bs[bk][bn] = bv;
        }
        __syncthreads();

        #pragma unroll
        for (int k = 0; k < GBK; k++) {
            float4 a0 = *(const float4*)&As[k][ty * 8];
            float4 a1 = *(const float4*)&As[k][ty * 8 + 4];
            ulonglong2 bb0 = *(const ulonglong2*)&Bs[k][tx * 8];
            ulonglong2 bb1 = *(const ulonglong2*)&Bs[k][tx * 8 + 4];
            ull bp[4] = {bb0.x, bb0.y, bb1.x, bb1.y};
            float av[8] = {a0.x, a0.y, a0.z, a0.w, a1.x, a1.y, a1.z, a1.w};
            #pragma unroll
            for (int i = 0; i < 8; i++) {
                ull ap;
                unsigned ai = __float_as_uint(av[i]);
                asm("mov.b64 %0, {%1, %1};" : "=l"(ap) : "r"(ai));
                #pragma unroll
                for (int j = 0; j < 4; j++)
                    asm("fma.rn.f32x2 %0, %1, %2, %0;"
                        : "+l"(acc[i][j]) : "l"(ap), "l"(bp[j]));
            }
        }
        __syncthreads();
    }

    #pragma unroll
    for (int i = 0; i < 8; i++) {
        int m = m0 + ty * 8 + i;
        if (m >= M) continue;
        #pragma unroll
        for (int j = 0; j < 4; j++) {
            unsigned lo, hi;
            asm("mov.b64 {%0, %1}, %2;" : "=r"(lo), "=r"(hi) : "l"(acc[i][j]));
            float vv[2] = {__uint_as_float(lo), __uint_as_float(hi)};
            #pragma unroll
            for (int q = 0; q < 2; q++) {
                int n = n0 + tx * 8 + 2 * j + q;
                if (n >= N) continue;
                float v = vv[q];
                int seg = n / 150;
                if (seg == 0 && bias0) v += bias0[n];
                if (seg == 1 && bias1) v += bias1[n - 150];
                if ((relu_mask >> seg) & 1) v = fmaxf(v, 0.f);
                C[(size_t)m * ldc + n] = v;
            }
        }
    }
}

// ---------------------------------------------------------------------------
// Attention output layer (warp per token)
// ---------------------------------------------------------------------------
__global__ void attn_out_kernel(const float* __restrict__ Hb,
                                const float* __restrict__ W3,
                                const float* __restrict__ b3,
                                float* __restrict__ out, int M)
{
    int gwarp = (blockIdx.x * blockDim.x + threadIdx.x) >> 5;
    int lane = threadIdx.x & 31;
    if (gwarp >= M) return;
    float acc = 0.f;
    #pragma unroll
    for (int k = lane; k < kH; k += 32)
        acc = fmaf(Hb[(size_t)gwarp * kH + k], W3[k], acc);
    #pragma unroll
    for (int o = 16; o > 0; o >>= 1)
        acc += __shfl_down_sync(0xffffffffu, acc, o);
    if (lane == 0) out[gwarp] = acc + b3[0];
}

// ---------------------------------------------------------------------------
// Prep: split W2 into padded bf16 hi/lo [160][160], pad b2/W3.
// ---------------------------------------------------------------------------
__global__ void prep_kernel(const float* __restrict__ W2,
                            const float* __restrict__ b2,
                            const float* __restrict__ W3,
                            __nv_bfloat16* __restrict__ W2s,
                            float* __restrict__ b2p, float* __restrict__ w3p)
{
    int i = blockIdx.x * blockDim.x + threadIdx.x;
    if (i < H1P * H1P) {
        int r = i / H1P, c = i % H1P;
        float w = (r < kH && c < kH) ? W2[r * kH + c] : 0.f;
        __nv_bfloat16 hi = __float2bfloat16(w);
        __nv_bfloat16 lo = __float2bfloat16(w - __bfloat162float(hi));
        W2s[i] = hi;
        W2s[H1P * H1P + i] = lo;
    }
    if (i < H1P) {
        b2p[i] = (i < kH) ? b2[i] : 0.f;
        w3p[i] = (i < kH) ? W3[i] : 0.f;
    }
}

// ---------------------------------------------------------------------------
// h1 assembly: width-specialized, 8 spans per batch, writes split-bf16 H1.
// ---------------------------------------------------------------------------
#define CH 8

__global__ __launch_bounds__(160) void h1_kernel(
    const float* __restrict__ attn,
    const float* __restrict__ tok,
    const float* __restrict__ Em,
    __nv_bfloat16* __restrict__ H1h, __nv_bfloat16* __restrict__ H1l)
{
    int n = blockIdx.y + 1;
    int S = kT - n + 1;
    int chunk = (S + gridDim.x - 1) / gridDim.x;
    int sa = blockIdx.x * chunk;
    int sb = min(sa + chunk, S);
    int off = (n - 1) * (kT + 1) - (n * (n - 1)) / 2;

    int h = threadIdx.x;
    bool act = h < kH;

    __shared__ float Esm[17][160];
    __shared__ float sw[CH][10];

    for (int s0 = sa; s0 < sb; s0 += CH) {
        int nsp = min(CH, sb - s0);
        int rows = n + nsp - 1;

        if (act)
            for (int r = 0; r < rows; r++)
                Esm[r][h] = Em[(size_t)(s0 + r) * kH + h];

        if (h < nsp) {
            int s = s0 + h;
            float w[10];
            float mx = -1e30f;
            for (int j = 0; j < n; j++) {
                float v = attn[s + j];
                w[j] = v;
                mx = fmaxf(mx, v);
            }
            float sum = 0.f;
            for (int j = 0; j < n; j++) {
                float e = __expf(w[j] - mx);
                w[j] = e;
                sum += e;
            }
            float inv = 1.f / sum;
            for (int j = 0; j < n; j++) sw[h][j] = w[j] * inv;
        }
        __syncthreads();

        if (act) {
            for (int sp = 0; sp < nsp; sp++) {
                int s = s0 + sp;
                float v = tok[(size_t)s * TOKW + 150 + h]
                        + tok[(size_t)(s + n - 1) * TOKW + 300 + h];
                for (int j = 0; j < n; j++)
                    v = fmaf(sw[sp][j], Esm[sp + j][h], v);
                v = fmaxf(v, 0.f);
                __nv_bfloat16 hi = __float2bfloat16(v);
                __nv_bfloat16 lo = __float2bfloat16(v - __bfloat162float(hi));
                size_t idx = (size_t)(off + s0 + sp) * H1P + h;
                H1h[idx] = hi;
                H1l[idx] = lo;
            }
        } else {  // pad cols 150..159
            for (int sp = 0; sp < nsp; sp++) {
                size_t idx = (size_t)(off + s0 + sp) * H1P + h;
                H1h[idx] = __float2bfloat16(0.f);
                H1l[idx] = __float2bfloat16(0.f);
            }
        }
        __syncthreads();
    }
}

// ---------------------------------------------------------------------------
// Score GEMM on tensor cores: mma.m16n8k16 bf16, split hi/lo 3-product.
// Block 128M x 160N, K=160 in 10 steps, 8 warps (4M x 2N), double-buffered.
// Fused epilogue: out[m] = sum_n relu(C+b2)*W3 + b3.
// ---------------------------------------------------------------------------
#define SCBM 128

__global__ __launch_bounds__(256, 1) void score_mma(
    const __nv_bfloat16* __restrict__ H1h, const __nv_bfloat16* __restrict__ H1l,
    const __nv_bfloat16* __restrict__ W2s,
    const float* __restrict__ b2p, const float* __restrict__ w3p,
    const float* __restrict__ b3,
    float* __restrict__ out, int M)
{
    // A staged at 24-half (48B) row stride; B at 168-half (336B) row stride.
    __shared__ __align__(16) __nv_bfloat16 As[2][2][128 * 24];
    __shared__ __align__(16) __nv_bfloat16 Bs[2][2][16 * 168];
    __shared__ float red[128][2];

    int tid = threadIdx.x;
    int m0 = blockIdx.x * SCBM;
    int wid = tid >> 5, lane = tid & 31;
    int warpM = wid & 3, warpN = wid >> 2;

    float C[2][10][4] = {};

    // ---- staging lambda (k-step ks into buffer buf) ----
    auto stage = [&](int ks, int buf) {
        int k0 = ks * 16;
        // A: 2 splits x 128 rows x 16 halfs = 512 chunks of 8 halfs (16B)
        #pragma unroll
        for (int c = tid; c < 512; c += 256) {
            int sp = c >> 8, tt = c & 255, r = tt >> 1, half = tt & 1;
            int mrow = min(m0 + r, M - 1);
            const __nv_bfloat16* src =
                (sp ? H1l : H1h) + (size_t)mrow * H1P + k0 + half * 8;
            *(int4*)&As[buf][sp][r * 24 + half * 8] = *(const int4*)src;
        }
        // B: 2 splits x 16 rows x 160 halfs = 640 chunks of 8 halfs
        for (int c = tid; c < 640; c += 256) {
            int sp = c / 320, cc = c % 320, row = cc / 20, offc = cc % 20;
            const __nv_bfloat16* src =
                W2s + (size_t)sp * H1P * H1P + (size_t)(k0 + row) * H1P + offc * 8;
            *(int4*)&Bs[buf][sp][row * 168 + offc * 8] = *(const int4*)src;
        }
    };

    stage(0, 0);
    __syncthreads();

    for (int ks = 0; ks < 10; ks++) {
        int buf = ks & 1;
        if (ks < 9) stage(ks + 1, buf ^ 1);

        // load A fragments: [split][mfrag][4]
        unsigned a[2][2][4];
        #pragma unroll
        for (int sp = 0; sp < 2; sp++)
            #pragma unroll
            for (int mf = 0; mf < 2; mf++) {
                unsigned addr = sm_u32(
                    &As[buf][sp][(warpM * 32 + mf * 16 + (lane & 15)) * 24 +
                                 (lane >> 4) * 8]);
                asm volatile(
                    "ldmatrix.sync.aligned.m8n8.x4.shared.b16 {%0,%1,%2,%3}, [%4];"
                    : "=r"(a[sp][mf][0]), "=r"(a[sp][mf][1]),
                      "=r"(a[sp][mf][2]), "=r"(a[sp][mf][3])
                    : "r"(addr));
            }

        #pragma unroll
        for (int np = 0; np < 5; np++) {
            int nbase = warpN * 80 + np * 16;
            unsigned bh[4], bl[4];
            {
                unsigned addr = sm_u32(
                    &Bs[buf][0][(lane & 15) * 168 + nbase + (lane >> 4) * 8]);
                asm volatile(
                    "ldmatrix.sync.aligned.m8n8.x4.trans.shared.b16 {%0,%1,%2,%3}, [%4];"
                    : "=r"(bh[0]), "=r"(bh[1]), "=r"(bh[2]), "=r"(bh[3])
                    : "r"(addr));
            }
            {
                unsigned addr = sm_u32(
                    &Bs[buf][1][(lane & 15) * 168 + nbase + (lane >> 4) * 8]);
                asm volatile(
                    "ldmatrix.sync.aligned.m8n8.x4.trans.shared.b16 {%0,%1,%2,%3}, [%4];"
                    : "=r"(bl[0]), "=r"(bl[1]), "=r"(bl[2]), "=r"(bl[3])
                    : "r"(addr));
            }
            #pragma unroll
            for (int mf = 0; mf < 2; mf++) {
                float* c0 = C[mf][2 * np];
                float* c1 = C[mf][2 * np + 1];
                // Ahi * Bhi
                asm volatile(
                    "mma.sync.aligned.m16n8k16.row.col.f32.bf16.bf16.f32 "
                    "{%0,%1,%2,%3},{%4,%5,%6,%7},{%8,%9},{%0,%1,%2,%3};"
                    : "+f"(c0[0]), "+f"(c0[1]), "+f"(c0[2]), "+f"(c0[3])
                    : "r"(a[0][mf][0]), "r"(a[0][mf][1]), "r"(a[0][mf][2]),
                      "r"(a[0][mf][3]), "r"(bh[0]), "r"(bh[1]));
                asm volatile(
                    "mma.sync.aligned.m16n8k16.row.col.f32.bf16.bf16.f32 "
                    "{%0,%1,%2,%3},{%4,%5,%6,%7},{%8,%9},{%0,%1,%2,%3};"
                    : "+f"(c1[0]), "+f"(c1[1]), "+f"(c1[2]), "+f"(c1[3])
                    : "r"(a[0][mf][0]), "r"(a[0][mf][1]), "r"(a[0][mf][2]),
                      "r"(a[0][mf][3]), "r"(bh[2]), "r"(bh[3]));
                // Alo * Bhi
                asm volatile(
                    "mma.sync.aligned.m16n8k16.row.col.f32.bf16.bf16.f32 "
                    "{%0,%1,%2,%3},{%4,%5,%6,%7},{%8,%9},{%0,%1,%2,%3};"
                    : "+f"(c0[0]), "+f"(c0[1]), "+f"(c0[2]), "+f"(c0[3])
                    : "r"(a[1][mf][0]), "r"(a[1][mf][1]), "r"(a[1][mf][2]),
                      "r"(a[1][mf][3]), "r"(bh[0]), "r"(bh[1]));
                asm volatile(
                    "mma.sync.aligned.m16n8k16.row.col.f32.bf16.bf16.f32 "
                    "{%0,%1,%2,%3},{%4,%5,%6,%7},{%8,%9},{%0,%1,%2,%3};"
                    : "+f"(c1[0]), "+f"(c1[1]), "+f"(c1[2]), "+f"(c1[3])
                    : "r"(a[1][mf][0]), "r"(a[1][mf][1]), "r"(a[1][mf][2]),
                      "r"(a[1][mf][3]), "r"(bh[2]), "r"(bh[3]));
                // Ahi * Blo
                asm volatile(
                    "mma.sync.aligned.m16n8k16.row.col.f32.bf16.bf16.f32 "
                    "{%0,%1,%2,%3},{%4,%5,%6,%7},{%8,%9},{%0,%1,%2,%3};"
                    : "+f"(c0[0]), "+f"(c0[1]), "+f"(c0[2]), "+f"(c0[3])
                    : "r"(a[0][mf][0]), "r"(a[0][mf][1]), "r"(a[0][mf][2]),
                      "r"(a[0][mf][3]), "r"(bl[0]), "r"(bl[1]));
                asm volatile(
                    "mma.sync.aligned.m16n8k16.row.col.f32.bf16.bf16.f32 "
                    "{%0,%1,%2,%3},{%4,%5,%6,%7},{%8,%9},{%0,%1,%2,%3};"
                    : "+f"(c1[0]), "+f"(c1[1]), "+f"(c1[2]), "+f"(c1[3])
                    : "r"(a[0][mf][0]), "r"(a[0][mf][1]), "r"(a[0][mf][2]),
                      "r"(a[0][mf][3]), "r"(bl[2]), "r"(bl[3]));
            }
        }
        __syncthreads();
    }

    // ---- epilogue ----
    int tq = lane & 3, g = lane >> 2;
    #pragma unroll
    for (int mf = 0; mf < 2; mf++) {
        float v0 = 0.f, v1 = 0.f;
        #pragma unroll
        for (int nf = 0; nf < 10; nf++) {
            int col = warpN * 80 + nf * 8 + tq * 2;
            float bb0 = __ldg(&b2p[col]), bb1 = __ldg(&b2p[col + 1]);
            float ww0 = __ldg(&w3p[col]), ww1 = __ldg(&w3p[col + 1]);
            float* c = C[mf][nf];
            v0 = fmaf(fmaxf(c[0] + bb0, 0.f), ww0, v0);
            v0 = fmaf(fmaxf(c[1] + bb1, 0.f), ww1, v0);
            v1 = fmaf(fmaxf(c[2] + bb0, 0.f), ww0, v1);
            v1 = fmaf(fmaxf(c[3] + bb1, 0.f), ww1, v1);
        }
        v0 += __shfl_xor_sync(0xffffffffu, v0, 1);
        v0 += __shfl_xor_sync(0xffffffffu, v0, 2);
        v1 += __shfl_xor_sync(0xffffffffu, v1, 1);
        v1 += __shfl_xor_sync(0xffffffffu, v1, 2);
        if (tq == 0) {
            red[warpM * 32 + mf * 16 + g][warpN] = v0;
            red[warpM * 32 + mf * 16 + g + 8][warpN] = v1;
        }
    }
    __syncthreads();
    if (tid < SCBM) {
        int m = m0 + tid;
        if (m < M) out[m] = red[tid][0] + red[tid][1] + b3[0];
    }
}

// ---------------------------------------------------------------------------
extern "C" void kernel_launch(void* const* d_in, const int* in_sizes, int n_in,
                              void* d_out, int out_size)
{
    const float* embeds = (const float*)d_in[0];
    const float* states = (const float*)d_in[1];
    const float* aW1 = (const float*)d_in[2];
    const float* ab1 = (const float*)d_in[3];
    const float* aW2 = (const float*)d_in[4];
    const float* ab2 = (const float*)d_in[5];
    const float* aW3 = (const float*)d_in[6];
    const float* ab3 = (const float*)d_in[7];
    const float* sW1 = (const float*)d_in[8];
    const float* sb1 = (const float*)d_in[9];
    const float* sW2 = (const float*)d_in[10];
    const float* sb2 = (const float*)d_in[11];
    const float* sW3 = (const float*)d_in[12];
    const float* sb3 = (const float*)d_in[13];
    float* out = (float*)d_out;

    float *tok, *Hb, *E, *attn, *b2p, *w3p;
    __nv_bfloat16 *H1h, *H1l, *W2s;
    cudaGetSymbolAddress((void**)&tok, g_tok);
    cudaGetSymbolAddress((void**)&Hb, g_Hb);
    cudaGetSymbolAddress((void**)&E, g_E);
    cudaGetSymbolAddress((void**)&attn, g_attn);
    cudaGetSymbolAddress((void**)&H1h, g_H1h);
    cudaGetSymbolAddress((void**)&H1l, g_H1l);
    cudaGetSymbolAddress((void**)&W2s, g_W2s);
    cudaGetSymbolAddress((void**)&b2p, g_b2p);
    cudaGetSymbolAddress((void**)&w3p, g_w3p);

    // prep W2 splits (independent)
    prep_kernel<<<(H1P * H1P + 255) / 256, 256>>>(sW2, sb2, sW3, W2s, b2p, w3p);

    // E = embeds @ sW1[800:1100]
    {
        dim3 g((kT + GBM - 1) / GBM, (kH + GBN - 1) / GBN);
        sgemm2<<<g, 256>>>(kT, kH, kE, embeds, kE,
                           sW1 + (size_t)800 * kH, nullptr, nullptr,
                           nullptr, nullptr, 0, E, kH);
    }
    // fused token GEMM: [Ha | A | B]
    {
        dim3 g((kT + GBM - 1) / GBM, (TOKW + GBN - 1) / GBN);
        sgemm2<<<g, 256>>>(kT, TOKW, kS, states, kS,
                           aW1, sW1, sW1 + (size_t)400 * kH,
                           ab1, sb1, 1, tok, TOKW);
    }
    // Hb = relu(Ha @ aW2 + ab2)
    {
        dim3 g((kT + GBM - 1) / GBM, (kH + GBN - 1) / GBN);
        sgemm2<<<g, 256>>>(kT, kH, kH, tok, TOKW,
                           aW2, nullptr, nullptr,
                           ab2, nullptr, 1, Hb, kH);
    }
    attn_out_kernel<<<(kT + 7) / 8, 256>>>(Hb, aW3, ab3, attn, kT);

    // h1 assembly -> split-bf16 H1
    h1_kernel<<<dim3(592, 10), 160>>>(attn, tok, E, H1h, H1l);

    // tensor-core score GEMM + fused epilogue
    score_mma<<<(NSPANS + SCBM - 1) / SCBM, 256>>>(H1h, H1l, W2s, b2p, w3p,
                                                   sb3, out, NSPANS);
}